// round 16
// baseline (speedup 1.0000x reference)
#include <cuda_runtime.h>

#define NB 32
#define CI 64
#define LT 300
#define V  25
#define KD 192

typedef unsigned long long ull;
typedef unsigned int uint;

// xwin (tf32 bits), layout [n][mpair(150)][c(64)][52]  (cols 25 & 51 stay 0)
__device__ float g_xwin2[(size_t)NB * 150 * CI * 52];
// pre-swizzled W A-fragments: [Mt(12)][ks(8)][lane(32)][4] tf32 bits
__device__ __align__(16) uint g_Wfrag[12 * 8 * 32 * 4];
// pre-swizzled GEMM2 B-fragments: [ks(10)][t(4)][lane(32)] -> (b0,b1) tf32 bits
__device__ __align__(16) ull  g_A2frag[10 * 4 * 32];
// BN constants: [inv(64), bias(64)]
__device__ __align__(16) float g_bn[2 * CI];

__device__ __forceinline__ uint f2tf(float f){
    uint u; asm("cvt.rna.tf32.f32 %0,%1;" : "=r"(u) : "f"(f)); return u;
}
__device__ __forceinline__ ull pack2u(uint lo, uint hi){
    ull r; asm("mov.b64 %0,{%1,%2};" : "=l"(r) : "r"(lo), "r"(hi)); return r;
}
__device__ __forceinline__ void unpack2u(ull v, uint& lo, uint& hi){
    asm("mov.b64 {%0,%1},%2;" : "=r"(lo), "=r"(hi) : "l"(v));
}
__device__ __forceinline__ void mma_tf32(float& d0, float& d1, float& d2, float& d3,
                                         uint a0, uint a1, uint a2, uint a3,
                                         uint b0, uint b1){
    asm volatile("mma.sync.aligned.m16n8k8.row.col.f32.tf32.tf32.f32 "
                 "{%0,%1,%2,%3},{%4,%5,%6,%7},{%8,%9},{%0,%1,%2,%3};"
                 : "+f"(d0), "+f"(d1), "+f"(d2), "+f"(d3)
                 : "r"(a0), "r"(a1), "r"(a2), "r"(a3), "r"(b0), "r"(b1));
}
__device__ __forceinline__ unsigned smem_u32(const void* p){
    unsigned a;
    asm("{ .reg .u64 t; cvta.to.shared.u64 t, %1; cvt.u32.u64 %0, t; }" : "=r"(a) : "l"(p));
    return a;
}

// ---------- kernel 1: window sum (L sliced x12) + one-time setup (block 0) ----------
#define WCG 8
#define WLQ 25
#define WTH (WCG * V)

__global__ __launch_bounds__(WTH) void win_kernel(
    const float* __restrict__ x,
    const float* __restrict__ A,
    const float* __restrict__ W,
    const float* __restrict__ gamma,
    const float* __restrict__ beta,
    const float* __restrict__ mean,
    const float* __restrict__ var)
{
    const int b = blockIdx.x;
    const int t = threadIdx.x;

    if (b == 0){
        if (t < CI){
            float inv = gamma[t] * rsqrtf(var[t] + 1e-3f);
            g_bn[t]      = inv;
            g_bn[CI + t] = beta[t] - mean[t]*inv;
        }
        for (int idx = t; idx < 12*8*32*4; idx += WTH){
            int j    = idx & 3;
            int lane = (idx >> 2) & 31;
            int ks   = (idx >> 7) & 7;
            int mt   = idx >> 10;
            int r  = mt*16 + (lane >> 2) + (j & 1)*8;
            int cc = ks*8  + (lane & 3)  + (j >> 1)*4;
            g_Wfrag[idx] = f2tf(W[cc*KD + r]);
        }
        for (int idx = t; idx < 10*4*32; idx += WTH){
            int lane = idx & 31;
            int tt   = (idx >> 5) & 3;
            int ks   = idx >> 7;
            int lq = lane & 3, lg = lane >> 2;
            int C0 = ks*8 + lq, C1 = C0 + 4;
            int wc = tt*8 + lg;
            uint b0 = 0, b1 = 0;
            if (wc < V){
                int p0 = C0/26, v0 = C0 - 26*p0;
                if (C0 < 78 && v0 < V) b0 = f2tf(A[(p0*V + v0)*V + wc]);
                int p1 = C1/26, v1 = C1 - 26*p1;
                if (C1 < 78 && v1 < V) b1 = f2tf(A[(p1*V + v1)*V + wc]);
            }
            g_A2frag[idx] = pack2u(b0, b1);
        }
    }

    const int n  = b / 96;
    const int r  = b - n*96;
    const int cg = r / 12;
    const int q  = r - cg*12;
    const int cl = t / V;
    const int v  = t - cl * V;
    const int c  = cg * WCG + cl;
    const int l0 = q * WLQ;

    const float* xp = x + ((size_t)(n * CI + c) * LT) * V + v;
    float* opb = g_xwin2 + ((size_t)n * 150 * CI + c) * 52 + v;

    float ring[9];
    #pragma unroll
    for (int j = 0; j < 9; j++) ring[j] = 0.f;
    float s = 0.f;

    #pragma unroll 1
    for (int base = 0; base < 36; base += 9) {
        #pragma unroll
        for (int j = 0; j < 9; j++) {
            int l = l0 - 8 + base + j;
            float nv = (l >= 0 && l < LT) ? xp[(size_t)l * V] : 0.f;
            s += nv - ring[j];
            ring[j] = nv;
            if (l >= l0 && l < l0 + WLQ)
                opb[(size_t)(l >> 1) * (CI*52) + (l & 1)*26] = __uint_as_float(f2tf(s));
        }
    }
}

// ---------- kernel 2: MT=4 fused dual tf32 GEMM + BN + ReLU + residual ----------
// block = (n, m-quad). 512 threads (16 warps), 1 block/SM.
// smem: xw [64][104] (B of GEMM1, stride 104 = 8 mod 32: conflict-free)
//       Yr [256][84] (GEMM2 A-layout: row = co*4 + m, col = p*26 + v, K pad 80)
#define TPB 512
#define XW_OFF 0
#define YR_OFF (XW_OFF + 64*104)
#define SM_WORDS (YR_OFF + 256*84)
#define MAIN_SMEM (SM_WORDS * 4)      // 112640 B

__global__ __launch_bounds__(TPB, 1) void main_kernel(
    const float* __restrict__ x,
    float* __restrict__ out)
{
    extern __shared__ float sm[];
    uint*  smu = (uint*)sm;

    const int tid  = threadIdx.x;
    const int wid  = tid >> 5;
    const int lane = tid & 31;
    const int lg   = lane >> 2;
    const int lq   = lane & 3;
    const int n    = blockIdx.x / 75;
    const int mq   = blockIdx.x % 75;
    const int m0   = mq * 4;

    // ---- staging: two adjacent mpair tiles (contiguous 26.6 KB) ----
    // src [mpl(2)][c(64)][52] -> dst xw[c][mpl*52 + j]; pad cols arrive as zeros
    {
        const unsigned sb = smem_u32(sm);
        const char* srcX = (const char*)(g_xwin2 + ((size_t)n*150 + mq*2) * (CI*52));
        #pragma unroll
        for (int j = 0; j < 4; j++){
            int idx = j*TPB + tid;
            if (idx < 1664){
                int c   = idx / 26;
                int r   = idx - c*26;
                int mpl = r / 13;
                int jj  = r - mpl*13;
                asm volatile("cp.async.ca.shared.global [%0], [%1], 16;"
                             :: "r"(sb + (unsigned)((c*104 + mpl*52 + jj*4)*4)),
                                "l"(srcX + ((size_t)(mpl*CI + c)*52 + jj*4)*4));
            }
        }
        asm volatile("cp.async.commit_group;");
    }
    // zero Yr pad cols 78..79 (256 rows x 2 cols = 512 words)
    sm[YR_OFF + (tid >> 1)*84 + 78 + (tid & 1)] = 0.f;
    asm volatile("cp.async.wait_group 0;");
    __syncthreads();

    // ---- GEMM1: Y[192, 104] = W^T @ xw ; 16 warps = mw(4 x 3Mt) x nw(4 x {4,3,3,3}Nt)
    {
        const int mw = wid >> 2;
        const int nw = wid & 3;
        const int nNt = (nw == 0) ? 4 : 3;
        const int ntBase = (nw == 0) ? 0 : (nw*3 + 1);
        const int mtB = mw * 3;

        float acc[3][4][4];
        #pragma unroll
        for (int i = 0; i < 3; i++)
            #pragma unroll
            for (int t = 0; t < 4; t++)
                #pragma unroll
                for (int e = 0; e < 4; e++) acc[i][t][e] = 0.f;

        uint4 aC[3], aN[3];
        #pragma unroll
        for (int i = 0; i < 3; i++)
            aC[i] = *(const uint4*)(g_Wfrag + (((mtB + i)*8 + 0)*32 + lane)*4);

        #pragma unroll
        for (int ks = 0; ks < 8; ks++){
            int ksn = (ks + 1) & 7;
            #pragma unroll
            for (int i = 0; i < 3; i++)
                aN[i] = *(const uint4*)(g_Wfrag + (((mtB + i)*8 + ksn)*32 + lane)*4);

            uint b0[4], b1[4];
            #pragma unroll
            for (int t = 0; t < 4; t++){
                if (t < nNt){
                    int nt = ntBase + t;
                    b0[t] = smu[XW_OFF + (ks*8 + lq    )*104 + nt*8 + lg];
                    b1[t] = smu[XW_OFF + (ks*8 + lq + 4)*104 + nt*8 + lg];
                }
            }
            #pragma unroll
            for (int i = 0; i < 3; i++)
                #pragma unroll
                for (int t = 0; t < 4; t++)
                    if (t < nNt)
                        mma_tf32(acc[i][t][0], acc[i][t][1], acc[i][t][2], acc[i][t][3],
                                 aC[i].x, aC[i].y, aC[i].z, aC[i].w, b0[t], b1[t]);
            #pragma unroll
            for (int i = 0; i < 3; i++) aC[i] = aN[i];
        }

        // scatter Y into GEMM2 A-layout: row = co*4 + m, col = p*26 + v
        #pragma unroll
        for (int i = 0; i < 3; i++){
            int k1  = (mtB + i)*16 + lg;
            int co1 = k1/3,  pp1 = k1 - co1*3;
            int k2  = k1 + 8;
            int co2 = k2/3,  pp2 = k2 - co2*3;
            #pragma unroll
            for (int t = 0; t < 4; t++)
                if (t < nNt){
                    int col0 = (ntBase + t)*8 + 2*lq;     // 0..102, even
                    int m  = col0 / 26;
                    int v  = col0 - 26*m;
                    *(ull*)(sm + YR_OFF + (co1*4 + m)*84 + pp1*26 + v) =
                        pack2u(f2tf(acc[i][t][0]), f2tf(acc[i][t][1]));
                    *(ull*)(sm + YR_OFF + (co2*4 + m)*84 + pp2*26 + v) =
                        pack2u(f2tf(acc[i][t][2]), f2tf(acc[i][t][3]));
                }
        }
    }
    __syncthreads();

    // ---- GEMM2: T[256, 32] = Yr[256, 80] @ A2pad[80, 32]; 16 warps x 1 Mtile ----
    {
        float acc2[4][4];
        #pragma unroll
        for (int t = 0; t < 4; t++)
            #pragma unroll
            for (int e = 0; e < 4; e++) acc2[t][e] = 0.f;

        const int R = wid*16 + lg;
        const uint* yr = smu + YR_OFF;

        ull bcur[4];
        #pragma unroll
        for (int t = 0; t < 4; t++) bcur[t] = g_A2frag[t*32 + lane];

        #pragma unroll
        for (int ks = 0; ks < 10; ks++){
            int ksn = (ks + 1 < 10) ? ks + 1 : 0;
            ull bnx[4];
            #pragma unroll
            for (int t = 0; t < 4; t++) bnx[t] = g_A2frag[(ksn*4 + t)*32 + lane];

            int C0 = ks*8 + lq;
            int C1 = C0 + 4;
            uint a0 = yr[ R     *84 + C0];
            uint a1 = yr[(R + 8)*84 + C0];
            uint a2 = yr[ R     *84 + C1];
            uint a3 = yr[(R + 8)*84 + C1];

            #pragma unroll
            for (int t = 0; t < 4; t++){
                uint b0, b1; unpack2u(bcur[t], b0, b1);
                mma_tf32(acc2[t][0], acc2[t][1], acc2[t][2], acc2[t][3],
                         a0, a1, a2, a3, b0, b1);
            }
            #pragma unroll
            for (int t = 0; t < 4; t++) bcur[t] = bnx[t];
        }

        // epilogue: BN + ReLU + residual + ReLU
        #pragma unroll
        for (int t = 0; t < 4; t++){
            int wc = t*8 + 2*lq;
            #pragma unroll
            for (int j = 0; j < 2; j++){
                int Rr = wid*16 + lg + 8*j;
                int co = Rr >> 2;
                int ml = Rr & 3;
                int m2 = m0 + ml;
                float d0 = acc2[t][2*j];
                float d1 = acc2[t][2*j + 1];
                float iv = __ldg(g_bn + co);
                float bb = __ldg(g_bn + 64 + co);
                size_t base = ((size_t)(n*CI + co)*LT + m2)*V;
                if (wc < V){
                    float r0 = fmaxf(fmaf(d0, iv, bb), 0.f);
                    out[base + wc] = fmaxf(r0 + __ldg(x + base + wc), 0.f);
                }
                if (wc + 1 < V){
                    float r1 = fmaxf(fmaf(d1, iv, bb), 0.f);
                    out[base + wc + 1] = fmaxf(r1 + __ldg(x + base + wc + 1), 0.f);
                }
            }
        }
    }
}

extern "C" void kernel_launch(void* const* d_in, const int* in_sizes, int n_in,
                              void* d_out, int out_size) {
    const float* x     = (const float*)d_in[0];
    const float* A     = (const float*)d_in[1];
    const float* W     = (const float*)d_in[2];
    const float* gamma = (const float*)d_in[3];
    const float* beta  = (const float*)d_in[4];
    const float* mean  = (const float*)d_in[5];
    const float* var   = (const float*)d_in[6];
    float* out = (float*)d_out;

    win_kernel<<<NB * 8 * 12, WTH>>>(x, A, W, gamma, beta, mean, var);

    cudaFuncSetAttribute(main_kernel, cudaFuncAttributeMaxDynamicSharedMemorySize, MAIN_SMEM);
    main_kernel<<<NB * 75, TPB, MAIN_SMEM>>>(x, out);
}

// round 17
// speedup vs baseline: 1.2861x; 1.2861x over previous
#include <cuda_runtime.h>
#include <cuda_fp16.h>

#define NB 32
#define CI 64
#define LT 300
#define V  25
#define KD 192

typedef unsigned long long ull;
typedef unsigned int uint;

// xwin fp16, layout [n][mpair(150)][c(64)][56]  (cols 25, 51..55 stay 0)
__device__ __half g_xwin_h[(size_t)NB * 150 * CI * 56];
// W A-fragments (m16n8k16 row-major): [Mt(12)][ks(4)][lane(32)][4] half2-as-uint
__device__ __align__(16) uint g_WfragH[12 * 4 * 32 * 4];
// GEMM2 B-fragments: [ks(5)][t(4)][lane(32)] -> (b0,b1) half2 pair
__device__ __align__(16) ull  g_A2fragH[5 * 4 * 32];
// BN constants: [inv(64), bias(64)]
__device__ __align__(16) float g_bn[2 * CI];

__device__ __forceinline__ uint pack_h2(float lo, float hi){
    __half2 h = __floats2half2_rn(lo, hi);
    return *reinterpret_cast<uint*>(&h);
}
__device__ __forceinline__ ull pack2u(uint lo, uint hi){
    ull r; asm("mov.b64 %0,{%1,%2};" : "=l"(r) : "r"(lo), "r"(hi)); return r;
}
__device__ __forceinline__ void unpack2u(ull v, uint& lo, uint& hi){
    asm("mov.b64 {%0,%1},%2;" : "=r"(lo), "=r"(hi) : "l"(v));
}
__device__ __forceinline__ void mma_f16(float& d0, float& d1, float& d2, float& d3,
                                        uint a0, uint a1, uint a2, uint a3,
                                        uint b0, uint b1){
    asm volatile("mma.sync.aligned.m16n8k16.row.col.f32.f16.f16.f32 "
                 "{%0,%1,%2,%3},{%4,%5,%6,%7},{%8,%9},{%0,%1,%2,%3};"
                 : "+f"(d0), "+f"(d1), "+f"(d2), "+f"(d3)
                 : "r"(a0), "r"(a1), "r"(a2), "r"(a3), "r"(b0), "r"(b1));
}
__device__ __forceinline__ void ldsm_x4_t(uint& r0, uint& r1, uint& r2, uint& r3, unsigned a){
    asm volatile("ldmatrix.sync.aligned.m8n8.x4.trans.shared.b16 {%0,%1,%2,%3},[%4];"
                 : "=r"(r0), "=r"(r1), "=r"(r2), "=r"(r3) : "r"(a));
}
__device__ __forceinline__ void ldsm_x2_t(uint& r0, uint& r1, unsigned a){
    asm volatile("ldmatrix.sync.aligned.m8n8.x2.trans.shared.b16 {%0,%1},[%2];"
                 : "=r"(r0), "=r"(r1) : "r"(a));
}
__device__ __forceinline__ unsigned smem_u32(const void* p){
    unsigned a;
    asm("{ .reg .u64 t; cvta.to.shared.u64 t, %1; cvt.u32.u64 %0, t; }" : "=r"(a) : "l"(p));
    return a;
}

// ---------- kernel 1: window sum (L sliced x12) + one-time setup (block 0) ----------
#define WCG 8
#define WLQ 25
#define WTH (WCG * V)

__global__ __launch_bounds__(WTH) void win_kernel(
    const float* __restrict__ x,
    const float* __restrict__ A,
    const float* __restrict__ W,
    const float* __restrict__ gamma,
    const float* __restrict__ beta,
    const float* __restrict__ mean,
    const float* __restrict__ var)
{
    const int b = blockIdx.x;
    const int t = threadIdx.x;

    if (b == 0){
        if (t < CI){
            float inv = gamma[t] * rsqrtf(var[t] + 1e-3f);
            g_bn[t]      = inv;
            g_bn[CI + t] = beta[t] - mean[t]*inv;
        }
        // W A-fragments (m16n8k16 row-major): A1[row=kout][col=c] = W[c][kout]
        for (int idx = t; idx < 12*4*32*4; idx += WTH){
            int j    = idx & 3;
            int lane = (idx >> 2) & 31;
            int ks   = (idx >> 7) & 3;
            int mt   = idx >> 9;
            int lg = lane >> 2, lq = lane & 3;
            int row = mt*16 + lg + (j & 1)*8;
            int kk  = ks*16 + 2*lq + (j >> 1)*8;
            g_WfragH[idx] = pack_h2(W[kk*KD + row], W[(kk+1)*KD + row]);
        }
        // GEMM2 B fragments: K padded to 80, k index C -> (p=C/26, v=C%26)
        for (int idx = t; idx < 5*4*32; idx += WTH){
            int lane = idx & 31;
            int tt   = (idx >> 5) & 3;
            int ks   = idx >> 7;
            int lq = lane & 3, lg = lane >> 2;
            int wc = tt*8 + lg;
            float f[4] = {0.f, 0.f, 0.f, 0.f};
            if (wc < V){
                #pragma unroll
                for (int e = 0; e < 4; e++){
                    int C = ks*16 + 2*lq + (e >> 1)*8 + (e & 1);
                    if (C < 78){
                        int p = C/26, v = C - 26*p;
                        if (v < V) f[e] = A[(p*V + v)*V + wc];
                    }
                }
            }
            g_A2fragH[idx] = pack2u(pack_h2(f[0], f[1]), pack_h2(f[2], f[3]));
        }
    }

    const int n  = b / 96;
    const int r  = b - n*96;
    const int cg = r / 12;
    const int q  = r - cg*12;
    const int cl = t / V;
    const int v  = t - cl * V;
    const int c  = cg * WCG + cl;
    const int l0 = q * WLQ;

    const float* xp = x + ((size_t)(n * CI + c) * LT) * V + v;
    __half* opb = g_xwin_h + ((size_t)n * 150 * CI + c) * 56 + v;

    float ring[9];
    #pragma unroll
    for (int j = 0; j < 9; j++) ring[j] = 0.f;
    float s = 0.f;

    #pragma unroll 1
    for (int base = 0; base < 36; base += 9) {
        #pragma unroll
        for (int j = 0; j < 9; j++) {
            int l = l0 - 8 + base + j;
            float nv = (l >= 0 && l < LT) ? xp[(size_t)l * V] : 0.f;
            s += nv - ring[j];
            ring[j] = nv;
            if (l >= l0 && l < l0 + WLQ)
                opb[(size_t)(l >> 1) * (CI*56) + (l & 1)*26] = __float2half_rn(s);
        }
    }
}

// ---------- kernel 2: fused dual fp16 GEMM + BN + ReLU + residual ----------
// block = (n, m-pair). 256 threads (8 warps), 2 blocks/SM.
// smem (halfs): xwh [64][56] @0 | Yr [128][88] @3584 (row = co*2+m, col = p*26+v, K pad 80)
#define TPB 256
#define YRW 1792                     // word offset of Yr
#define SM_WORDS (1792 + 128*44)     // 7424 words = 29696 B
#define MAIN_SMEM (SM_WORDS * 4)

__global__ __launch_bounds__(TPB, 2) void main_kernel(
    const float* __restrict__ x,
    float* __restrict__ out)
{
    extern __shared__ float sm[];
    uint*  smu = (uint*)sm;
    __half* smh = (__half*)sm;

    const int tid  = threadIdx.x;
    const int wid  = tid >> 5;
    const int lane = tid & 31;
    const int lg   = lane >> 2;
    const int lq   = lane & 3;
    const int n    = blockIdx.x / 150;
    const int mp   = blockIdx.x % 150;
    const int m0   = mp * 2;
    const unsigned sb = smem_u32(sm);

    // ---- staging: xwh tile 64 x 112B = 448 x 16B, fully coalesced ----
    {
        const char* srcX = (const char*)(g_xwin_h + ((size_t)n*150 + mp) * (CI*56));
        #pragma unroll
        for (int j = 0; j < 2; j++){
            int idx = j*TPB + tid;
            if (idx < 448){
                int c  = idx / 7;
                int jj = idx - c*7;
                asm volatile("cp.async.ca.shared.global [%0], [%1], 16;"
                             :: "r"(sb + (unsigned)(c*112 + jj*16)),
                                "l"(srcX + (size_t)c*112 + jj*16));
            }
        }
        asm volatile("cp.async.commit_group;");
    }
    // zero Yr pad cols 78..79 (one uint per row)
    if (tid < 128) smu[YRW + tid*44 + 39] = 0;
    asm volatile("cp.async.wait_group 0;");
    __syncthreads();

    // ---- GEMM1: Y[192, 52] = W^T @ xw ; warp (mw, nw): 3 Mt x (4|3) Nt, K=64 (4 ksteps) ----
    {
        const int mw = wid >> 1;
        const int nw = wid & 1;
        const int nNt = nw ? 3 : 4;
        const int ntBase = nw * 4;
        const int mtB = mw * 3;

        float acc[3][4][4];
        #pragma unroll
        for (int i = 0; i < 3; i++)
            #pragma unroll
            for (int t = 0; t < 4; t++)
                #pragma unroll
                for (int e = 0; e < 4; e++) acc[i][t][e] = 0.f;

        uint4 aC[3], aN[3];
        #pragma unroll
        for (int i = 0; i < 3; i++)
            aC[i] = *(const uint4*)(g_WfragH + (((mtB + i)*4 + 0)*32 + lane)*4);

        #pragma unroll
        for (int ks = 0; ks < 4; ks++){
            int ksn = (ks + 1) & 3;
            #pragma unroll
            for (int i = 0; i < 3; i++)
                aN[i] = *(const uint4*)(g_WfragH + (((mtB + i)*4 + ksn)*32 + lane)*4);

            // B fragments via ldmatrix.trans from k-major fp16 xw (stride 56 halfs)
            unsigned rowAddr = sb + (unsigned)(((ks*16 + (lane & 15))*56)*2);
            uint b0[4], b1[4];
            if (nw == 0){
                ldsm_x4_t(b0[0], b1[0], b0[1], b1[1], rowAddr + (unsigned)(((lane >> 4)*8)*2));
                ldsm_x4_t(b0[2], b1[2], b0[3], b1[3], rowAddr + (unsigned)((16 + (lane >> 4)*8)*2));
            } else {
                ldsm_x4_t(b0[0], b1[0], b0[1], b1[1], rowAddr + (unsigned)((32 + (lane >> 4)*8)*2));
                ldsm_x2_t(b0[2], b1[2], rowAddr + (unsigned)(48*2));
            }

            #pragma unroll
            for (int i = 0; i < 3; i++)
                #pragma unroll
                for (int t = 0; t < 4; t++)
                    if (t < nNt)
                        mma_f16(acc[i][t][0], acc[i][t][1], acc[i][t][2], acc[i][t][3],
                                aC[i].x, aC[i].y, aC[i].z, aC[i].w, b0[t], b1[t]);
            #pragma unroll
            for (int i = 0; i < 3; i++) aC[i] = aN[i];
        }

        // scatter Y (fp16 pairs) into GEMM2 A-layout: row = co*2+m, col = p*26+v
        #pragma unroll
        for (int i = 0; i < 3; i++){
            int k1  = (mtB + i)*16 + lg;
            int co1 = k1/3,  pp1 = k1 - co1*3;
            int k2  = k1 + 8;
            int co2 = k2/3,  pp2 = k2 - co2*3;
            #pragma unroll
            for (int t = 0; t < 4; t++)
                if (t < nNt){
                    int col0 = (ntBase + t)*8 + 2*lq;
                    if (col0 < 52){
                        int m = (col0 >= 26) ? 1 : 0;
                        int v = col0 - 26*m;
                        smu[YRW + (co1*2 + m)*44 + pp1*13 + (v >> 1)] =
                            pack_h2(acc[i][t][0], acc[i][t][1]);
                        smu[YRW + (co2*2 + m)*44 + pp2*13 + (v >> 1)] =
                            pack_h2(acc[i][t][2], acc[i][t][3]);
                    }
                }
        }
    }
    __syncthreads();

    // ---- GEMM2: T[128, 32] = Yr[128, 80] @ A2pad[80, 32]; warp = Mtile, K=80 (5 ksteps) ----
    {
        float acc2[4][4];
        #pragma unroll
        for (int t = 0; t < 4; t++)
            #pragma unroll
            for (int e = 0; e < 4; e++) acc2[t][e] = 0.f;

        const int R = wid*16 + lg;

        ull bcur[4];
        #pragma unroll
        for (int t = 0; t < 4; t++) bcur[t] = g_A2fragH[t*32 + lane];

        #pragma unroll
        for (int ks = 0; ks < 5; ks++){
            int ksn = (ks + 1 < 5) ? ks + 1 : 0;
            ull bnx[4];
            #pragma unroll
            for (int t = 0; t < 4; t++) bnx[t] = g_A2fragH[(ksn*4 + t)*32 + lane];

            uint a0 = smu[YRW +  R     *44 + ks*8 + lq];
            uint a1 = smu[YRW + (R + 8)*44 + ks*8 + lq];
            uint a2 = smu[YRW +  R     *44 + ks*8 + lq + 4];
            uint a3 = smu[YRW + (R + 8)*44 + ks*8 + lq + 4];

            #pragma unroll
            for (int t = 0; t < 4; t++){
                uint b0, b1; unpack2u(bcur[t], b0, b1);
                mma_f16(acc2[t][0], acc2[t][1], acc2[t][2], acc2[t][3],
                        a0, a1, a2, a3, b0, b1);
            }
            #pragma unroll
            for (int t = 0; t < 4; t++) bcur[t] = bnx[t];
        }

        // epilogue: BN + ReLU + residual + ReLU
        #pragma unroll
        for (int t = 0; t < 4; t++){
            int wc = t*8 + 2*lq;
            #pragma unroll
            for (int j = 0; j < 2; j++){
                int Rr = wid*16 + lg + 8*j;
                int co = Rr >> 1;
                int ml = Rr & 1;
                int m2 = m0 + ml;
                float d0 = acc2[t][2*j];
                float d1 = acc2[t][2*j + 1];
                float iv = __ldg(g_bn + co);
                float bb = __ldg(g_bn + 64 + co);
                size_t base = ((size_t)(n*CI + co)*LT + m2)*V;
                if (wc < V){
                    float r0 = fmaxf(fmaf(d0, iv, bb), 0.f);
                    out[base + wc] = fmaxf(r0 + __ldg(x + base + wc), 0.f);
                }
                if (wc + 1 < V){
                    float r1 = fmaxf(fmaf(d1, iv, bb), 0.f);
                    out[base + wc + 1] = fmaxf(r1 + __ldg(x + base + wc + 1), 0.f);
                }
            }
        }
    }
    (void)smh;
}

extern "C" void kernel_launch(void* const* d_in, const int* in_sizes, int n_in,
                              void* d_out, int out_size) {
    const float* x     = (const float*)d_in[0];
    const float* A     = (const float*)d_in[1];
    const float* W     = (const float*)d_in[2];
    const float* gamma = (const float*)d_in[3];
    const float* beta  = (const float*)d_in[4];
    const float* mean  = (const float*)d_in[5];
    const float* var   = (const float*)d_in[6];
    float* out = (float*)d_out;

    win_kernel<<<NB * 8 * 12, WTH>>>(x, A, W, gamma, beta, mean, var);

    cudaFuncSetAttribute(main_kernel, cudaFuncAttributeMaxDynamicSharedMemorySize, MAIN_SMEM);
    main_kernel<<<NB * 150, TPB, MAIN_SMEM>>>(x, out);
}